// round 1
// baseline (speedup 1.0000x reference)
#include <cuda_runtime.h>
#include <math.h>

#define N_TOK 4096
#define D_DIM 1024
#define E_NUM 8
#define I_DIM 1408
#define PAIRS (N_TOK * 2)
#define MT_MAX 128   // ceil(PAIRS/64) worst-case M tiles per expert

// ---------------- device scratch (static: allocation-guard safe) -------------
__device__ int   d_topk_idx[N_TOK * 2];
__device__ float d_topk_prob[N_TOK * 2];
__device__ int   d_counts[E_NUM];
__device__ int   d_offsets[E_NUM + 1];
__device__ int   d_cursor[E_NUM];
__device__ int   d_pair_token[PAIRS];
__device__ float d_pair_prob[PAIRS];
__device__ int   d_pair_pos[N_TOK * 2];
__device__ float d_H[(size_t)PAIRS * I_DIM];      // 46.1 MB
__device__ float d_Ypart[(size_t)PAIRS * D_DIM];  // 33.6 MB

// ---------------- init -------------------------------------------------------
__global__ void init_kernel() {
    if (threadIdx.x < E_NUM) d_counts[threadIdx.x] = 0;
}

// ---------------- router: scores, top-2, softmax, counts ---------------------
__global__ void router_kernel(const float* __restrict__ x,
                              const float* __restrict__ gw) {
    __shared__ float xs[D_DIM];
    __shared__ float sc[E_NUM];
    int t = blockIdx.x;
    const float* xp = x + (size_t)t * D_DIM;
    for (int i = threadIdx.x; i < D_DIM; i += blockDim.x) xs[i] = xp[i];
    __syncthreads();
    int w = threadIdx.x >> 5, lane = threadIdx.x & 31;
    // 8 warps, one expert each
    float s = 0.f;
    const float* g = gw + (size_t)w * D_DIM;
    for (int j = lane; j < D_DIM; j += 32) s += xs[j] * g[j];
    #pragma unroll
    for (int o = 16; o; o >>= 1) s += __shfl_xor_sync(0xffffffffu, s, o);
    if (lane == 0) sc[w] = s;
    __syncthreads();
    if (threadIdx.x == 0) {
        int i0 = 0; float s0 = sc[0];
        #pragma unroll
        for (int e = 1; e < E_NUM; e++) if (sc[e] > s0) { s0 = sc[e]; i0 = e; }
        int i1 = -1; float s1 = -1e30f;
        #pragma unroll
        for (int e = 0; e < E_NUM; e++)
            if (e != i0 && sc[e] > s1) { s1 = sc[e]; i1 = e; }
        float z  = expf(s1 - s0);
        float p0 = 1.f / (1.f + z);
        float p1 = z * p0;
        d_topk_idx[t * 2]     = i0;  d_topk_idx[t * 2 + 1]  = i1;
        d_topk_prob[t * 2]    = p0;  d_topk_prob[t * 2 + 1] = p1;
        atomicAdd(&d_counts[i0], 1);
        atomicAdd(&d_counts[i1], 1);
    }
}

// ---------------- scan (E=8, single thread) ----------------------------------
__global__ void scan_kernel() {
    int off = 0;
    #pragma unroll
    for (int e = 0; e < E_NUM; e++) {
        d_offsets[e] = off;
        d_cursor[e]  = off;
        off += d_counts[e];
    }
    d_offsets[E_NUM] = off;
}

// ---------------- scatter tokens into per-expert lists -----------------------
__global__ void scatter_kernel() {
    int t = blockIdx.x * blockDim.x + threadIdx.x;
    if (t >= N_TOK) return;
    #pragma unroll
    for (int k = 0; k < 2; k++) {
        int e = d_topk_idx[t * 2 + k];
        int pos = atomicAdd(&d_cursor[e], 1);
        d_pair_token[pos]     = t;
        d_pair_prob[pos]      = d_topk_prob[t * 2 + k];
        d_pair_pos[t * 2 + k] = pos;
    }
}

// ---------------- gemm1: H = silu(Xg @ Wg^T) * (Xg @ Wu^T), gathered ---------
// Tile 64(M) x 64(N) x 16(K), 256 threads, 4x4 per thread, fused gate+up.
__global__ __launch_bounds__(256) void gemm1_kernel(
    const float* __restrict__ x,
    const float* __restrict__ wg,
    const float* __restrict__ wu) {
    int e  = blockIdx.y >> 7;
    int mt = blockIdx.y & (MT_MAX - 1);
    int cnt = d_counts[e];
    int m0  = mt * 64;
    if (m0 >= cnt) return;
    int n0   = blockIdx.x * 64;
    int base = d_offsets[e];

    __shared__ float As[16][68];
    __shared__ float Bg[16][68];
    __shared__ float Bu[16][68];
    __shared__ int   rowtok[64];

    int tid = threadIdx.x;
    if (tid < 64) {
        int r = m0 + tid;
        rowtok[tid] = (r < cnt) ? d_pair_token[base + r] : -1;
    }
    __syncthreads();

    int tx = tid & 15, ty = tid >> 4;
    float accG[4][4] = {}, accU[4][4] = {};

    const float* wgE = wg + (size_t)e * I_DIM * D_DIM;
    const float* wuE = wu + (size_t)e * I_DIM * D_DIM;

    int lm = tid >> 2;          // 0..63 : A-row / B-n index
    int lk = (tid & 3) * 4;     // k offset within tile

    for (int k0 = 0; k0 < D_DIM; k0 += 16) {
        int tok = rowtok[lm];
        float4 av = make_float4(0.f, 0.f, 0.f, 0.f);
        if (tok >= 0)
            av = *(const float4*)(x + (size_t)tok * D_DIM + k0 + lk);
        As[lk + 0][lm] = av.x; As[lk + 1][lm] = av.y;
        As[lk + 2][lm] = av.z; As[lk + 3][lm] = av.w;

        float4 gv = *(const float4*)(wgE + (size_t)(n0 + lm) * D_DIM + k0 + lk);
        Bg[lk + 0][lm] = gv.x; Bg[lk + 1][lm] = gv.y;
        Bg[lk + 2][lm] = gv.z; Bg[lk + 3][lm] = gv.w;

        float4 uv = *(const float4*)(wuE + (size_t)(n0 + lm) * D_DIM + k0 + lk);
        Bu[lk + 0][lm] = uv.x; Bu[lk + 1][lm] = uv.y;
        Bu[lk + 2][lm] = uv.z; Bu[lk + 3][lm] = uv.w;
        __syncthreads();

        #pragma unroll
        for (int kk = 0; kk < 16; kk++) {
            float4 a4  = *(const float4*)&As[kk][ty * 4];
            float4 g4  = *(const float4*)&Bg[kk][tx * 4];
            float4 u4  = *(const float4*)&Bu[kk][tx * 4];
            float a[4] = {a4.x, a4.y, a4.z, a4.w};
            float bg[4] = {g4.x, g4.y, g4.z, g4.w};
            float bu[4] = {u4.x, u4.y, u4.z, u4.w};
            #pragma unroll
            for (int i = 0; i < 4; i++)
                #pragma unroll
                for (int j = 0; j < 4; j++) {
                    accG[i][j] += a[i] * bg[j];
                    accU[i][j] += a[i] * bu[j];
                }
        }
        __syncthreads();
    }

    #pragma unroll
    for (int i = 0; i < 4; i++) {
        int r = m0 + ty * 4 + i;
        if (r >= cnt) break;
        size_t out = (size_t)(base + r) * I_DIM + n0 + tx * 4;
        #pragma unroll
        for (int j = 0; j < 4; j++) {
            float g = accG[i][j];
            float h = g / (1.f + expf(-g)) * accU[i][j];
            d_H[out + j] = h;
        }
    }
}

// ---------------- gemm2: Ypart = prob * (H @ Wd^T) ---------------------------
__global__ __launch_bounds__(256) void gemm2_kernel(
    const float* __restrict__ wd) {
    int e  = blockIdx.y >> 7;
    int mt = blockIdx.y & (MT_MAX - 1);
    int cnt = d_counts[e];
    int m0  = mt * 64;
    if (m0 >= cnt) return;
    int n0   = blockIdx.x * 64;
    int base = d_offsets[e];

    __shared__ float As[16][68];
    __shared__ float Bs[16][68];
    __shared__ float rowprob[64];

    int tid = threadIdx.x;
    if (tid < 64) {
        int r = m0 + tid;
        rowprob[tid] = (r < cnt) ? d_pair_prob[base + r] : 0.f;
    }

    int tx = tid & 15, ty = tid >> 4;
    float acc[4][4] = {};

    const float* wdE = wd + (size_t)e * D_DIM * I_DIM;

    int lm = tid >> 2;
    int lk = (tid & 3) * 4;
    int arow = m0 + lm;
    bool avalid = (arow < cnt);
    const float* aptr = d_H + (size_t)(base + arow) * I_DIM + lk;

    for (int k0 = 0; k0 < I_DIM; k0 += 16) {
        float4 av = make_float4(0.f, 0.f, 0.f, 0.f);
        if (avalid) av = *(const float4*)(aptr + k0);
        As[lk + 0][lm] = av.x; As[lk + 1][lm] = av.y;
        As[lk + 2][lm] = av.z; As[lk + 3][lm] = av.w;

        float4 bv = *(const float4*)(wdE + (size_t)(n0 + lm) * I_DIM + k0 + lk);
        Bs[lk + 0][lm] = bv.x; Bs[lk + 1][lm] = bv.y;
        Bs[lk + 2][lm] = bv.z; Bs[lk + 3][lm] = bv.w;
        __syncthreads();

        #pragma unroll
        for (int kk = 0; kk < 16; kk++) {
            float4 a4 = *(const float4*)&As[kk][ty * 4];
            float4 b4 = *(const float4*)&Bs[kk][tx * 4];
            float a[4] = {a4.x, a4.y, a4.z, a4.w};
            float b[4] = {b4.x, b4.y, b4.z, b4.w};
            #pragma unroll
            for (int i = 0; i < 4; i++)
                #pragma unroll
                for (int j = 0; j < 4; j++)
                    acc[i][j] += a[i] * b[j];
        }
        __syncthreads();
    }

    #pragma unroll
    for (int i = 0; i < 4; i++) {
        int r = m0 + ty * 4 + i;
        if (r >= cnt) break;
        float p = rowprob[ty * 4 + i];
        size_t out = (size_t)(base + r) * D_DIM + n0 + tx * 4;
        #pragma unroll
        for (int j = 0; j < 4; j++)
            d_Ypart[out + j] = p * acc[i][j];
    }
}

// ---------------- combine: y = partial(slot0) + partial(slot1) ---------------
__global__ void combine_kernel(float* __restrict__ y) {
    int i = blockIdx.x * blockDim.x + threadIdx.x;  // over N_TOK * D/4
    int t = i / (D_DIM / 4);
    int c = (i % (D_DIM / 4)) * 4;
    int p0 = d_pair_pos[t * 2];
    int p1 = d_pair_pos[t * 2 + 1];
    float4 a = *(const float4*)&d_Ypart[(size_t)p0 * D_DIM + c];
    float4 b = *(const float4*)&d_Ypart[(size_t)p1 * D_DIM + c];
    float4 o = make_float4(a.x + b.x, a.y + b.y, a.z + b.z, a.w + b.w);
    *(float4*)&y[(size_t)t * D_DIM + c] = o;
}

// ---------------- launch -----------------------------------------------------
extern "C" void kernel_launch(void* const* d_in, const int* in_sizes, int n_in,
                              void* d_out, int out_size) {
    const float* x  = (const float*)d_in[0];
    const float* gw = (const float*)d_in[1];
    const float* wg = (const float*)d_in[2];
    const float* wu = (const float*)d_in[3];
    const float* wd = (const float*)d_in[4];
    float* y = (float*)d_out;

    init_kernel<<<1, 32>>>();
    router_kernel<<<N_TOK, 256>>>(x, gw);
    scan_kernel<<<1, 1>>>();
    scatter_kernel<<<(N_TOK + 255) / 256, 256>>>();
    gemm1_kernel<<<dim3(I_DIM / 64, E_NUM * MT_MAX), 256>>>(x, wg, wu);
    gemm2_kernel<<<dim3(D_DIM / 64, E_NUM * MT_MAX), 256>>>(wd);
    combine_kernel<<<(N_TOK * D_DIM / 4 + 255) / 256, 256>>>(y);
}

// round 4
// speedup vs baseline: 2.1435x; 2.1435x over previous
#include <cuda_runtime.h>
#include <cuda_bf16.h>
#include <math.h>
#include <stdint.h>

#define N_TOK 4096
#define D_DIM 1024
#define E_NUM 8
#define I_DIM 1408
#define PAIRS (N_TOK * 2)
#define MT_MAX 64
#define AS 24   // bf16 per smem row: 16 data + 8 pad (48B, conflict-free)

#define W_ELEMS ((size_t)E_NUM * I_DIM * D_DIM)

// ---------------- device scratch (static: allocation-guard safe) -------------
__device__ int   d_topk_idx[N_TOK * 2];
__device__ float d_topk_prob[N_TOK * 2];
__device__ int   d_counts[E_NUM];
__device__ int   d_offsets[E_NUM + 1];
__device__ int   d_cursor[E_NUM];
__device__ int   d_pair_token[PAIRS];
__device__ float d_pair_prob[PAIRS];
__device__ int   d_pair_pos[N_TOK * 2];
__device__ float d_Ypart[(size_t)PAIRS * D_DIM];            // 33.6 MB

// split bf16 planes: [0]=hi, [1]=lo
__device__ __nv_bfloat16 s_x [2][(size_t)N_TOK * D_DIM];    // 16 MB
__device__ __nv_bfloat16 s_wg[2][W_ELEMS];                  // 46 MB
__device__ __nv_bfloat16 s_wu[2][W_ELEMS];                  // 46 MB
__device__ __nv_bfloat16 s_wd[2][W_ELEMS];                  // 46 MB
__device__ __nv_bfloat16 s_H [2][(size_t)PAIRS * I_DIM];    // 46 MB

// ---------------- PTX helpers ------------------------------------------------
__device__ __forceinline__ void cp16b(__nv_bfloat16* dst_smem, const __nv_bfloat16* src, bool pred) {
    uint32_t d = (uint32_t)__cvta_generic_to_shared(dst_smem);
    int sz = pred ? 16 : 0;
    asm volatile("cp.async.cg.shared.global [%0], [%1], 16, %2;\n"
                 :: "r"(d), "l"(src), "r"(sz));
}
__device__ __forceinline__ void cp_commit() {
    asm volatile("cp.async.commit_group;\n");
}
template <int N>
__device__ __forceinline__ void cp_wait() {
    asm volatile("cp.async.wait_group %0;\n" :: "n"(N));
}
__device__ __forceinline__ void mma_bf16(float c[4],
                                         uint32_t a0, uint32_t a1, uint32_t a2, uint32_t a3,
                                         uint32_t b0, uint32_t b1) {
    asm volatile(
        "mma.sync.aligned.m16n8k16.row.col.f32.bf16.bf16.f32 "
        "{%0,%1,%2,%3}, {%4,%5,%6,%7}, {%8,%9}, {%0,%1,%2,%3};\n"
        : "+f"(c[0]), "+f"(c[1]), "+f"(c[2]), "+f"(c[3])
        : "r"(a0), "r"(a1), "r"(a2), "r"(a3), "r"(b0), "r"(b1));
}

// ---------------- split: fp32 -> bf16 hi/lo planes ---------------------------
__global__ void split_kernel(const float4* __restrict__ src,
                             uint2* __restrict__ hi, uint2* __restrict__ lo, int n4) {
    int i = blockIdx.x * blockDim.x + threadIdx.x;
    if (i >= n4) return;
    float4 v = src[i];
    __nv_bfloat16 h0 = __float2bfloat16_rn(v.x);
    __nv_bfloat16 h1 = __float2bfloat16_rn(v.y);
    __nv_bfloat16 h2 = __float2bfloat16_rn(v.z);
    __nv_bfloat16 h3 = __float2bfloat16_rn(v.w);
    __nv_bfloat16 l0 = __float2bfloat16_rn(v.x - __bfloat162float(h0));
    __nv_bfloat16 l1 = __float2bfloat16_rn(v.y - __bfloat162float(h1));
    __nv_bfloat16 l2 = __float2bfloat16_rn(v.z - __bfloat162float(h2));
    __nv_bfloat16 l3 = __float2bfloat16_rn(v.w - __bfloat162float(h3));
    __nv_bfloat162 hA = __halves2bfloat162(h0, h1), hB = __halves2bfloat162(h2, h3);
    __nv_bfloat162 lA = __halves2bfloat162(l0, l1), lB = __halves2bfloat162(l2, l3);
    uint2 ho, loo;
    ho.x  = *(uint32_t*)&hA;  ho.y  = *(uint32_t*)&hB;
    loo.x = *(uint32_t*)&lA;  loo.y = *(uint32_t*)&lB;
    hi[i] = ho;
    lo[i] = loo;
}

// ---------------- init -------------------------------------------------------
__global__ void init_kernel() {
    if (threadIdx.x < E_NUM) d_counts[threadIdx.x] = 0;
}

// ---------------- router -----------------------------------------------------
__global__ void router_kernel(const float* __restrict__ x,
                              const float* __restrict__ gw) {
    __shared__ float xs[D_DIM];
    __shared__ float sc[E_NUM];
    int t = blockIdx.x;
    const float* xp = x + (size_t)t * D_DIM;
    for (int i = threadIdx.x; i < D_DIM; i += blockDim.x) xs[i] = xp[i];
    __syncthreads();
    int w = threadIdx.x >> 5, lane = threadIdx.x & 31;
    float s = 0.f;
    const float* g = gw + (size_t)w * D_DIM;
    for (int j = lane; j < D_DIM; j += 32) s += xs[j] * g[j];
    #pragma unroll
    for (int o = 16; o; o >>= 1) s += __shfl_xor_sync(0xffffffffu, s, o);
    if (lane == 0) sc[w] = s;
    __syncthreads();
    if (threadIdx.x == 0) {
        int i0 = 0; float s0 = sc[0];
        #pragma unroll
        for (int e = 1; e < E_NUM; e++) if (sc[e] > s0) { s0 = sc[e]; i0 = e; }
        int i1 = -1; float s1 = -1e30f;
        #pragma unroll
        for (int e = 0; e < E_NUM; e++)
            if (e != i0 && sc[e] > s1) { s1 = sc[e]; i1 = e; }
        float z  = expf(s1 - s0);
        float p0 = 1.f / (1.f + z);
        float p1 = z * p0;
        d_topk_idx[t * 2]     = i0;  d_topk_idx[t * 2 + 1]  = i1;
        d_topk_prob[t * 2]    = p0;  d_topk_prob[t * 2 + 1] = p1;
        atomicAdd(&d_counts[i0], 1);
        atomicAdd(&d_counts[i1], 1);
    }
}

// ---------------- scan / scatter ---------------------------------------------
__global__ void scan_kernel() {
    int off = 0;
    #pragma unroll
    for (int e = 0; e < E_NUM; e++) {
        d_offsets[e] = off;
        d_cursor[e]  = off;
        off += d_counts[e];
    }
    d_offsets[E_NUM] = off;
}

__global__ void scatter_kernel() {
    int t = blockIdx.x * blockDim.x + threadIdx.x;
    if (t >= N_TOK) return;
    #pragma unroll
    for (int k = 0; k < 2; k++) {
        int e = d_topk_idx[t * 2 + k];
        int pos = atomicAdd(&d_cursor[e], 1);
        d_pair_token[pos]     = t;
        d_pair_prob[pos]      = d_topk_prob[t * 2 + k];
        d_pair_pos[t * 2 + k] = pos;
    }
}

// =============================================================================
// gemm1: H = silu(Xg @ Wg^T) * (Xg @ Wu^T)  — split bf16, 3-MMA emulated fp32
// Block 128(M) x 64(N) x 16(K), 256 threads, warp tile 64x16.
// =============================================================================
struct Smem1 {
    __nv_bfloat16 Ah[2][128 * AS], Al[2][128 * AS];
    __nv_bfloat16 Bgh[2][64 * AS], Bgl[2][64 * AS];
    __nv_bfloat16 Buh[2][64 * AS], Bul[2][64 * AS];
    int rowtok[128];
};

__global__ __launch_bounds__(256) void gemm1_kernel() {
    extern __shared__ char smem_raw[];
    Smem1& S = *reinterpret_cast<Smem1*>(smem_raw);

    int e  = blockIdx.y >> 6;
    int mt = blockIdx.y & (MT_MAX - 1);
    int cnt = d_counts[e];
    int m0  = mt * 128;
    if (m0 >= cnt) return;
    int n0   = blockIdx.x * 64;
    int base = d_offsets[e];

    int tid = threadIdx.x;
    if (tid < 128) {
        int r = m0 + tid;
        S.rowtok[tid] = (r < cnt) ? d_pair_token[base + r] : -1;
    }
    __syncthreads();

    // cp.async assignments
    int a_row = tid >> 1;          // 0..127
    int a_c   = tid & 1;           // 8-elem chunk
    int tokA  = S.rowtok[a_row];
    const __nv_bfloat16* gxh = s_x[0] + (size_t)(tokA < 0 ? 0 : tokA) * D_DIM + a_c * 8;
    const __nv_bfloat16* gxl = s_x[1] + (size_t)(tokA < 0 ? 0 : tokA) * D_DIM + a_c * 8;
    bool apred = tokA >= 0;

    int b_row = tid >> 2;          // 0..63
    int b_c   = (tid >> 1) & 1;
    int b_p   = tid & 1;           // plane
    size_t wE = (size_t)e * I_DIM * D_DIM;
    const __nv_bfloat16* gbg = (b_p ? s_wg[1] : s_wg[0]) + wE + (size_t)(n0 + b_row) * D_DIM + b_c * 8;
    const __nv_bfloat16* gbu = (b_p ? s_wu[1] : s_wu[0]) + wE + (size_t)(n0 + b_row) * D_DIM + b_c * 8;

    int wid = tid >> 5, lane = tid & 31;
    int wm0 = (wid >> 2) * 64, wn0 = (wid & 3) * 16;
    int g   = lane >> 2, tg = lane & 3;

    float accG[4][2][4], accU[4][2][4];
    #pragma unroll
    for (int i = 0; i < 4; i++)
        #pragma unroll
        for (int j = 0; j < 2; j++)
            #pragma unroll
            for (int k = 0; k < 4; k++) { accG[i][j][k] = 0.f; accU[i][j][k] = 0.f; }

    const int T = D_DIM / 16;   // 64

    {
        cp16b(&S.Ah[0][a_row * AS + a_c * 8], gxh, apred);
        cp16b(&S.Al[0][a_row * AS + a_c * 8], gxl, apred);
        __nv_bfloat16* dg = (b_p ? S.Bgl[0] : S.Bgh[0]);
        __nv_bfloat16* du = (b_p ? S.Bul[0] : S.Buh[0]);
        cp16b(&dg[b_row * AS + b_c * 8], gbg, true);
        cp16b(&du[b_row * AS + b_c * 8], gbu, true);
        cp_commit();
    }

    for (int t = 0; t < T; t++) {
        if (t + 1 < T) {
            int buf = (t + 1) & 1;
            int k0 = (t + 1) * 16;
            cp16b(&S.Ah[buf][a_row * AS + a_c * 8], gxh + k0, apred);
            cp16b(&S.Al[buf][a_row * AS + a_c * 8], gxl + k0, apred);
            __nv_bfloat16* dg = (b_p ? S.Bgl[buf] : S.Bgh[buf]);
            __nv_bfloat16* du = (b_p ? S.Bul[buf] : S.Buh[buf]);
            cp16b(&dg[b_row * AS + b_c * 8], gbg + k0, true);
            cp16b(&du[b_row * AS + b_c * 8], gbu + k0, true);
            cp_commit();
            cp_wait<1>();
        } else {
            cp_wait<0>();
        }
        __syncthreads();

        int buf = t & 1;
        const __nv_bfloat16* ah  = S.Ah[buf];
        const __nv_bfloat16* al  = S.Al[buf];
        const __nv_bfloat16* bgh = S.Bgh[buf];
        const __nv_bfloat16* bgl = S.Bgl[buf];
        const __nv_bfloat16* buh = S.Buh[buf];
        const __nv_bfloat16* bul = S.Bul[buf];

        uint32_t afh[4][4], afl[4][4];
        #pragma unroll
        for (int mi = 0; mi < 4; mi++) {
            int r = wm0 + mi * 16 + g;
            afh[mi][0] = *(const uint32_t*)&ah[r * AS + 2 * tg];
            afh[mi][1] = *(const uint32_t*)&ah[(r + 8) * AS + 2 * tg];
            afh[mi][2] = *(const uint32_t*)&ah[r * AS + 8 + 2 * tg];
            afh[mi][3] = *(const uint32_t*)&ah[(r + 8) * AS + 8 + 2 * tg];
            afl[mi][0] = *(const uint32_t*)&al[r * AS + 2 * tg];
            afl[mi][1] = *(const uint32_t*)&al[(r + 8) * AS + 2 * tg];
            afl[mi][2] = *(const uint32_t*)&al[r * AS + 8 + 2 * tg];
            afl[mi][3] = *(const uint32_t*)&al[(r + 8) * AS + 8 + 2 * tg];
        }
        #pragma unroll
        for (int ni = 0; ni < 2; ni++) {
            int c = wn0 + ni * 8 + g;
            uint32_t bgh0 = *(const uint32_t*)&bgh[c * AS + 2 * tg];
            uint32_t bgh1 = *(const uint32_t*)&bgh[c * AS + 8 + 2 * tg];
            uint32_t bgl0 = *(const uint32_t*)&bgl[c * AS + 2 * tg];
            uint32_t bgl1 = *(const uint32_t*)&bgl[c * AS + 8 + 2 * tg];
            uint32_t buh0 = *(const uint32_t*)&buh[c * AS + 2 * tg];
            uint32_t buh1 = *(const uint32_t*)&buh[c * AS + 8 + 2 * tg];
            uint32_t bul0 = *(const uint32_t*)&bul[c * AS + 2 * tg];
            uint32_t bul1 = *(const uint32_t*)&bul[c * AS + 8 + 2 * tg];
            #pragma unroll
            for (int mi = 0; mi < 4; mi++) {
                mma_bf16(accG[mi][ni], afh[mi][0], afh[mi][1], afh[mi][2], afh[mi][3], bgh0, bgh1);
                mma_bf16(accG[mi][ni], afh[mi][0], afh[mi][1], afh[mi][2], afh[mi][3], bgl0, bgl1);
                mma_bf16(accG[mi][ni], afl[mi][0], afl[mi][1], afl[mi][2], afl[mi][3], bgh0, bgh1);
                mma_bf16(accU[mi][ni], afh[mi][0], afh[mi][1], afh[mi][2], afh[mi][3], buh0, buh1);
                mma_bf16(accU[mi][ni], afh[mi][0], afh[mi][1], afh[mi][2], afh[mi][3], bul0, bul1);
                mma_bf16(accU[mi][ni], afl[mi][0], afl[mi][1], afl[mi][2], afl[mi][3], buh0, buh1);
            }
        }
        __syncthreads();
    }

    // epilogue: silu(g)*u -> split bf16 planes of H
    #pragma unroll
    for (int mi = 0; mi < 4; mi++) {
        #pragma unroll
        for (int ni = 0; ni < 2; ni++) {
            int col = n0 + wn0 + ni * 8 + tg * 2;
            #pragma unroll
            for (int half = 0; half < 2; half++) {
                int r = m0 + wm0 + mi * 16 + g + half * 8;
                if (r < cnt) {
                    size_t out = (size_t)(base + r) * I_DIM + col;
                    float gv0 = accG[mi][ni][half * 2];
                    float gv1 = accG[mi][ni][half * 2 + 1];
                    float h0 = gv0 / (1.f + expf(-gv0)) * accU[mi][ni][half * 2];
                    float h1 = gv1 / (1.f + expf(-gv1)) * accU[mi][ni][half * 2 + 1];
                    __nv_bfloat16 H0 = __float2bfloat16_rn(h0);
                    __nv_bfloat16 H1 = __float2bfloat16_rn(h1);
                    __nv_bfloat16 L0 = __float2bfloat16_rn(h0 - __bfloat162float(H0));
                    __nv_bfloat16 L1 = __float2bfloat16_rn(h1 - __bfloat162float(H1));
                    *(__nv_bfloat162*)&s_H[0][out] = __halves2bfloat162(H0, H1);
                    *(__nv_bfloat162*)&s_H[1][out] = __halves2bfloat162(L0, L1);
                }
            }
        }
    }
}

// =============================================================================
// gemm2: Ypart = prob * (H @ Wd^T) — split bf16, 3-MMA
// Block 128(M) x 128(N) x 16(K), 256 threads, warp tile 64x32.
// =============================================================================
struct Smem2 {
    __nv_bfloat16 Ah[2][128 * AS], Al[2][128 * AS];
    __nv_bfloat16 Bh[2][128 * AS], Bl[2][128 * AS];
    float rowprob[128];
};

__global__ __launch_bounds__(256) void gemm2_kernel() {
    extern __shared__ char smem_raw[];
    Smem2& S = *reinterpret_cast<Smem2*>(smem_raw);

    int e  = blockIdx.y >> 6;
    int mt = blockIdx.y & (MT_MAX - 1);
    int cnt = d_counts[e];
    int m0  = mt * 128;
    if (m0 >= cnt) return;
    int n0   = blockIdx.x * 128;
    int base = d_offsets[e];

    int tid = threadIdx.x;
    if (tid < 128) {
        int r = m0 + tid;
        S.rowprob[tid] = (r < cnt) ? d_pair_prob[base + r] : 0.f;
    }
    __syncthreads();

    int a_row = tid >> 1;
    int a_c   = tid & 1;
    bool av = (m0 + a_row) < cnt;
    size_t arow_g = (size_t)(base + (av ? m0 + a_row : 0)) * I_DIM + a_c * 8;
    const __nv_bfloat16* gah = s_H[0] + arow_g;
    const __nv_bfloat16* gal = s_H[1] + arow_g;

    size_t wE = (size_t)e * D_DIM * I_DIM;
    size_t brow_g = wE + (size_t)(n0 + a_row) * I_DIM + a_c * 8;
    const __nv_bfloat16* gbh = s_wd[0] + brow_g;
    const __nv_bfloat16* gbl = s_wd[1] + brow_g;

    int wid = tid >> 5, lane = tid & 31;
    int wm0 = (wid >> 2) * 64, wn0 = (wid & 3) * 32;
    int g   = lane >> 2, tg = lane & 3;

    float acc[4][4][4];
    #pragma unroll
    for (int i = 0; i < 4; i++)
        #pragma unroll
        for (int j = 0; j < 4; j++)
            #pragma unroll
            for (int k = 0; k < 4; k++) acc[i][j][k] = 0.f;

    const int T = I_DIM / 16;   // 88

    {
        cp16b(&S.Ah[0][a_row * AS + a_c * 8], gah, av);
        cp16b(&S.Al[0][a_row * AS + a_c * 8], gal, av);
        cp16b(&S.Bh[0][a_row * AS + a_c * 8], gbh, true);
        cp16b(&S.Bl[0][a_row * AS + a_c * 8], gbl, true);
        cp_commit();
    }

    for (int t = 0; t < T; t++) {
        if (t + 1 < T) {
            int buf = (t + 1) & 1;
            int k0 = (t + 1) * 16;
            cp16b(&S.Ah[buf][a_row * AS + a_c * 8], gah + k0, av);
            cp16b(&S.Al[buf][a_row * AS + a_c * 8], gal + k0, av);
            cp16b(&S.Bh[buf][a_row * AS + a_c * 8], gbh + k0, true);
            cp16b(&S.Bl[buf][a_row * AS + a_c * 8], gbl + k0, true);
            cp_commit();
            cp_wait<1>();
        } else {
            cp_wait<0>();
        }
        __syncthreads();

        int buf = t & 1;
        const __nv_bfloat16* ah = S.Ah[buf];
        const __nv_bfloat16* al = S.Al[buf];
        const __nv_bfloat16* bh = S.Bh[buf];
        const __nv_bfloat16* bl = S.Bl[buf];

        uint32_t afh[4][4], afl[4][4];
        #pragma unroll
        for (int mi = 0; mi < 4; mi++) {
            int r = wm0 + mi * 16 + g;
            afh[mi][0] = *(const uint32_t*)&ah[r * AS + 2 * tg];
            afh[mi][1] = *(const uint32_t*)&ah[(r + 8) * AS + 2 * tg];
            afh[mi][2] = *(const uint32_t*)&ah[r * AS + 8 + 2 * tg];
            afh[mi][3] = *(const uint32_t*)&ah[(r + 8) * AS + 8 + 2 * tg];
            afl[mi][0] = *(const uint32_t*)&al[r * AS + 2 * tg];
            afl[mi][1] = *(const uint32_t*)&al[(r + 8) * AS + 2 * tg];
            afl[mi][2] = *(const uint32_t*)&al[r * AS + 8 + 2 * tg];
            afl[mi][3] = *(const uint32_t*)&al[(r + 8) * AS + 8 + 2 * tg];
        }
        #pragma unroll
        for (int ni = 0; ni < 4; ni++) {
            int c = wn0 + ni * 8 + g;
            uint32_t bh0 = *(const uint32_t*)&bh[c * AS + 2 * tg];
            uint32_t bh1 = *(const uint32_t*)&bh[c * AS + 8 + 2 * tg];
            uint32_t bl0 = *(const uint32_t*)&bl[c * AS + 2 * tg];
            uint32_t bl1 = *(const uint32_t*)&bl[c * AS + 8 + 2 * tg];
            #pragma unroll
            for (int mi = 0; mi < 4; mi++) {
                mma_bf16(acc[mi][ni], afh[mi][0], afh[mi][1], afh[mi][2], afh[mi][3], bh0, bh1);
                mma_bf16(acc[mi][ni], afh[mi][0], afh[mi][1], afh[mi][2], afh[mi][3], bl0, bl1);
                mma_bf16(acc[mi][ni], afl[mi][0], afl[mi][1], afl[mi][2], afl[mi][3], bh0, bh1);
            }
        }
        __syncthreads();
    }

    // epilogue: scale by prob -> d_Ypart (fp32)
    #pragma unroll
    for (int mi = 0; mi < 4; mi++) {
        #pragma unroll
        for (int half = 0; half < 2; half++) {
            int rb = wm0 + mi * 16 + g + half * 8;
            int r  = m0 + rb;
            if (r >= cnt) continue;
            float p = S.rowprob[rb];
            size_t out = (size_t)(base + r) * D_DIM + n0 + wn0;
            #pragma unroll
            for (int ni = 0; ni < 4; ni++) {
                int col = ni * 8 + tg * 2;
                d_Ypart[out + col]     = p * acc[mi][ni][half * 2];
                d_Ypart[out + col + 1] = p * acc[mi][ni][half * 2 + 1];
            }
        }
    }
}

// ---------------- combine ----------------------------------------------------
__global__ void combine_kernel(float* __restrict__ y) {
    int i = blockIdx.x * blockDim.x + threadIdx.x;
    int t = i / (D_DIM / 4);
    int c = (i % (D_DIM / 4)) * 4;
    int p0 = d_pair_pos[t * 2];
    int p1 = d_pair_pos[t * 2 + 1];
    float4 a = *(const float4*)&d_Ypart[(size_t)p0 * D_DIM + c];
    float4 b = *(const float4*)&d_Ypart[(size_t)p1 * D_DIM + c];
    float4 o = make_float4(a.x + b.x, a.y + b.y, a.z + b.z, a.w + b.w);
    *(float4*)&y[(size_t)t * D_DIM + c] = o;
}

// ---------------- launch -----------------------------------------------------
extern "C" void kernel_launch(void* const* d_in, const int* in_sizes, int n_in,
                              void* d_out, int out_size) {
    const float* x  = (const float*)d_in[0];
    const float* gw = (const float*)d_in[1];
    const float* wg = (const float*)d_in[2];
    const float* wu = (const float*)d_in[3];
    const float* wd = (const float*)d_in[4];
    float* y = (float*)d_out;

    cudaFuncSetAttribute(gemm1_kernel, cudaFuncAttributeMaxDynamicSharedMemorySize, sizeof(Smem1));
    cudaFuncSetAttribute(gemm2_kernel, cudaFuncAttributeMaxDynamicSharedMemorySize, sizeof(Smem2));

    __nv_bfloat16 *p_x, *p_wg, *p_wu, *p_wd;
    cudaGetSymbolAddress((void**)&p_x,  s_x);
    cudaGetSymbolAddress((void**)&p_wg, s_wg);
    cudaGetSymbolAddress((void**)&p_wu, s_wu);
    cudaGetSymbolAddress((void**)&p_wd, s_wd);
    size_t xN = (size_t)N_TOK * D_DIM;

    init_kernel<<<1, 32>>>();
    router_kernel<<<N_TOK, 256>>>(x, gw);

    {   // splits
        int n4 = (int)(xN / 4);
        split_kernel<<<(n4 + 255) / 256, 256>>>((const float4*)x, (uint2*)p_x, (uint2*)(p_x + xN), n4);
        int w4 = (int)(W_ELEMS / 4);
        const float* wsrc[3] = {wg, wu, wd};
        __nv_bfloat16* wdst[3] = {p_wg, p_wu, p_wd};
        for (int m = 0; m < 3; m++)
            split_kernel<<<(w4 + 255) / 256, 256>>>((const float4*)wsrc[m],
                                                    (uint2*)wdst[m],
                                                    (uint2*)(wdst[m] + W_ELEMS), w4);
    }

    scan_kernel<<<1, 1>>>();
    scatter_kernel<<<(N_TOK + 255) / 256, 256>>>();
    gemm1_kernel<<<dim3(I_DIM / 64, E_NUM * MT_MAX), 256, sizeof(Smem1)>>>();
    gemm2_kernel<<<dim3(D_DIM / 128, E_NUM * MT_MAX), 256, sizeof(Smem2)>>>();
    combine_kernel<<<(N_TOK * D_DIM / 4 + 255) / 256, 256>>>(y);
}

// round 5
// speedup vs baseline: 2.4662x; 1.1506x over previous
#include <cuda_runtime.h>
#include <cuda_bf16.h>
#include <math.h>
#include <stdint.h>

#define N_TOK 4096
#define D_DIM 1024
#define E_NUM 8
#define I_DIM 1408
#define PAIRS (N_TOK * 2)
#define MT_MAX 64
#define AS2 40   // bf16 per smem row: 32 data + 8 pad (80B = 5x16B, ldsm conflict-free)

#define W_ELEMS ((size_t)E_NUM * I_DIM * D_DIM)

// ---------------- device scratch (static: allocation-guard safe) -------------
__device__ int   d_topk_idx[N_TOK * 2];
__device__ float d_topk_prob[N_TOK * 2];
__device__ int   d_counts[E_NUM];
__device__ int   d_offsets[E_NUM + 1];
__device__ int   d_cursor[E_NUM];
__device__ int   d_pair_token[PAIRS];
__device__ float d_pair_prob[PAIRS];
__device__ int   d_pair_pos[N_TOK * 2];
__device__ float d_Ypart[(size_t)PAIRS * D_DIM];            // 33.6 MB

// split bf16 planes: [0]=hi, [1]=lo
__device__ __nv_bfloat16 s_x [2][(size_t)N_TOK * D_DIM];
__device__ __nv_bfloat16 s_wg[2][W_ELEMS];
__device__ __nv_bfloat16 s_wu[2][W_ELEMS];
__device__ __nv_bfloat16 s_wd[2][W_ELEMS];
__device__ __nv_bfloat16 s_H [2][(size_t)PAIRS * I_DIM];

// ---------------- PTX helpers ------------------------------------------------
__device__ __forceinline__ void cp16b(__nv_bfloat16* dst_smem, const __nv_bfloat16* src, bool pred) {
    uint32_t d = (uint32_t)__cvta_generic_to_shared(dst_smem);
    int sz = pred ? 16 : 0;
    asm volatile("cp.async.cg.shared.global [%0], [%1], 16, %2;\n"
                 :: "r"(d), "l"(src), "r"(sz));
}
__device__ __forceinline__ void cp_commit() {
    asm volatile("cp.async.commit_group;\n");
}
template <int N>
__device__ __forceinline__ void cp_wait() {
    asm volatile("cp.async.wait_group %0;\n" :: "n"(N));
}
__device__ __forceinline__ void mma_bf16(float c[4],
                                         uint32_t a0, uint32_t a1, uint32_t a2, uint32_t a3,
                                         uint32_t b0, uint32_t b1) {
    asm volatile(
        "mma.sync.aligned.m16n8k16.row.col.f32.bf16.bf16.f32 "
        "{%0,%1,%2,%3}, {%4,%5,%6,%7}, {%8,%9}, {%0,%1,%2,%3};\n"
        : "+f"(c[0]), "+f"(c[1]), "+f"(c[2]), "+f"(c[3])
        : "r"(a0), "r"(a1), "r"(a2), "r"(a3), "r"(b0), "r"(b1));
}
__device__ __forceinline__ void ldsm4(uint32_t& r0, uint32_t& r1, uint32_t& r2, uint32_t& r3,
                                      const __nv_bfloat16* p) {
    uint32_t a = (uint32_t)__cvta_generic_to_shared(p);
    asm volatile("ldmatrix.sync.aligned.m8n8.x4.shared.b16 {%0,%1,%2,%3}, [%4];\n"
                 : "=r"(r0), "=r"(r1), "=r"(r2), "=r"(r3) : "r"(a));
}

// ---------------- split: fp32 -> bf16 hi/lo planes ---------------------------
__global__ void split_kernel(const float4* __restrict__ src,
                             uint2* __restrict__ hi, uint2* __restrict__ lo, int n4) {
    int i = blockIdx.x * blockDim.x + threadIdx.x;
    if (i >= n4) return;
    float4 v = src[i];
    __nv_bfloat16 h0 = __float2bfloat16_rn(v.x);
    __nv_bfloat16 h1 = __float2bfloat16_rn(v.y);
    __nv_bfloat16 h2 = __float2bfloat16_rn(v.z);
    __nv_bfloat16 h3 = __float2bfloat16_rn(v.w);
    __nv_bfloat16 l0 = __float2bfloat16_rn(v.x - __bfloat162float(h0));
    __nv_bfloat16 l1 = __float2bfloat16_rn(v.y - __bfloat162float(h1));
    __nv_bfloat16 l2 = __float2bfloat16_rn(v.z - __bfloat162float(h2));
    __nv_bfloat16 l3 = __float2bfloat16_rn(v.w - __bfloat162float(h3));
    __nv_bfloat162 hA = __halves2bfloat162(h0, h1), hB = __halves2bfloat162(h2, h3);
    __nv_bfloat162 lA = __halves2bfloat162(l0, l1), lB = __halves2bfloat162(l2, l3);
    uint2 ho, loo;
    ho.x  = *(uint32_t*)&hA;  ho.y  = *(uint32_t*)&hB;
    loo.x = *(uint32_t*)&lA;  loo.y = *(uint32_t*)&lB;
    hi[i] = ho;
    lo[i] = loo;
}

// ---------------- init / router / scan / scatter ------------------------------
__global__ void init_kernel() {
    if (threadIdx.x < E_NUM) d_counts[threadIdx.x] = 0;
}

__global__ void router_kernel(const float* __restrict__ x,
                              const float* __restrict__ gw) {
    __shared__ float xs[D_DIM];
    __shared__ float sc[E_NUM];
    int t = blockIdx.x;
    const float* xp = x + (size_t)t * D_DIM;
    for (int i = threadIdx.x; i < D_DIM; i += blockDim.x) xs[i] = xp[i];
    __syncthreads();
    int w = threadIdx.x >> 5, lane = threadIdx.x & 31;
    float s = 0.f;
    const float* g = gw + (size_t)w * D_DIM;
    for (int j = lane; j < D_DIM; j += 32) s += xs[j] * g[j];
    #pragma unroll
    for (int o = 16; o; o >>= 1) s += __shfl_xor_sync(0xffffffffu, s, o);
    if (lane == 0) sc[w] = s;
    __syncthreads();
    if (threadIdx.x == 0) {
        int i0 = 0; float s0 = sc[0];
        #pragma unroll
        for (int e = 1; e < E_NUM; e++) if (sc[e] > s0) { s0 = sc[e]; i0 = e; }
        int i1 = -1; float s1 = -1e30f;
        #pragma unroll
        for (int e = 0; e < E_NUM; e++)
            if (e != i0 && sc[e] > s1) { s1 = sc[e]; i1 = e; }
        float z  = expf(s1 - s0);
        float p0 = 1.f / (1.f + z);
        float p1 = z * p0;
        d_topk_idx[t * 2]     = i0;  d_topk_idx[t * 2 + 1]  = i1;
        d_topk_prob[t * 2]    = p0;  d_topk_prob[t * 2 + 1] = p1;
        atomicAdd(&d_counts[i0], 1);
        atomicAdd(&d_counts[i1], 1);
    }
}

__global__ void scan_kernel() {
    int off = 0;
    #pragma unroll
    for (int e = 0; e < E_NUM; e++) {
        d_offsets[e] = off;
        d_cursor[e]  = off;
        off += d_counts[e];
    }
    d_offsets[E_NUM] = off;
}

__global__ void scatter_kernel() {
    int t = blockIdx.x * blockDim.x + threadIdx.x;
    if (t >= N_TOK) return;
    #pragma unroll
    for (int k = 0; k < 2; k++) {
        int e = d_topk_idx[t * 2 + k];
        int pos = atomicAdd(&d_cursor[e], 1);
        d_pair_token[pos]     = t;
        d_pair_prob[pos]      = d_topk_prob[t * 2 + k];
        d_pair_pos[t * 2 + k] = pos;
    }
}

// =============================================================================
// gemm1: H = silu(Xg @ Wg^T) * (Xg @ Wu^T) — split bf16, 3-MMA, ldmatrix, K=32
// Block 128(M) x 64(N) x 32(K), 256 threads, warp tile 64x16.
// =============================================================================
struct Smem1 {
    __nv_bfloat16 Ah[2][128 * AS2], Al[2][128 * AS2];
    __nv_bfloat16 Bgh[2][64 * AS2], Bgl[2][64 * AS2];
    __nv_bfloat16 Buh[2][64 * AS2], Bul[2][64 * AS2];
    int rowtok[128];
};

__global__ __launch_bounds__(256) void gemm1_kernel() {
    extern __shared__ char smem_raw[];
    Smem1& S = *reinterpret_cast<Smem1*>(smem_raw);

    int e  = blockIdx.y >> 6;
    int mt = blockIdx.y & (MT_MAX - 1);
    int cnt = d_counts[e];
    int m0  = mt * 128;
    if (m0 >= cnt) return;
    int n0   = blockIdx.x * 64;
    int base = d_offsets[e];

    int tid = threadIdx.x;
    if (tid < 128) {
        int r = m0 + tid;
        S.rowtok[tid] = (r < cnt) ? d_pair_token[base + r] : -1;
    }
    __syncthreads();

    // cp.async: A rows (tid>>2, +64) x chunk (tid&3) x 2 planes = 4 ops/thread
    int ld_row = tid >> 2;           // 0..63
    int ld_c   = (tid & 3) * 8;      // col offset in bf16
    int tokA0 = S.rowtok[ld_row];
    int tokA1 = S.rowtok[ld_row + 64];
    const __nv_bfloat16* gx0h = s_x[0] + (size_t)(tokA0 < 0 ? 0 : tokA0) * D_DIM + ld_c;
    const __nv_bfloat16* gx0l = s_x[1] + (size_t)(tokA0 < 0 ? 0 : tokA0) * D_DIM + ld_c;
    const __nv_bfloat16* gx1h = s_x[0] + (size_t)(tokA1 < 0 ? 0 : tokA1) * D_DIM + ld_c;
    const __nv_bfloat16* gx1l = s_x[1] + (size_t)(tokA1 < 0 ? 0 : tokA1) * D_DIM + ld_c;
    bool ap0 = tokA0 >= 0, ap1 = tokA1 >= 0;

    // B: row (tid>>2, 0..63) x chunk x {gate,up}x{hi,lo} = 4 ops/thread
    size_t wE = (size_t)e * I_DIM * D_DIM;
    size_t bro = wE + (size_t)(n0 + ld_row) * D_DIM + ld_c;
    const __nv_bfloat16* gbgh = s_wg[0] + bro;
    const __nv_bfloat16* gbgl = s_wg[1] + bro;
    const __nv_bfloat16* gbuh = s_wu[0] + bro;
    const __nv_bfloat16* gbul = s_wu[1] + bro;

    int wid = tid >> 5, lane = tid & 31;
    int wm0 = (wid >> 2) * 64, wn0 = (wid & 3) * 16;
    // ldmatrix lane offsets (bf16 elems)
    int a_loff = ((lane & 7) + ((lane >> 3) & 1) * 8) * AS2 + ((lane >> 4) & 1) * 8;
    int b_loff = ((lane & 7) + ((lane >> 4) & 1) * 8) * AS2 + ((lane >> 3) & 1) * 8;
    int g  = lane >> 2, tg = lane & 3;

    float accG[4][2][4], accU[4][2][4];
    #pragma unroll
    for (int i = 0; i < 4; i++)
        #pragma unroll
        for (int j = 0; j < 2; j++)
            #pragma unroll
            for (int k = 0; k < 4; k++) { accG[i][j][k] = 0.f; accU[i][j][k] = 0.f; }

    const int TS = D_DIM / 32;   // 32 stages

    int ld_dst = ld_row * AS2 + ld_c;
    // prefetch stage 0
    {
        cp16b(&S.Ah[0][ld_dst], gx0h, ap0);
        cp16b(&S.Al[0][ld_dst], gx0l, ap0);
        cp16b(&S.Ah[0][ld_dst + 64 * AS2], gx1h, ap1);
        cp16b(&S.Al[0][ld_dst + 64 * AS2], gx1l, ap1);
        cp16b(&S.Bgh[0][ld_dst], gbgh, true);
        cp16b(&S.Bgl[0][ld_dst], gbgl, true);
        cp16b(&S.Buh[0][ld_dst], gbuh, true);
        cp16b(&S.Bul[0][ld_dst], gbul, true);
        cp_commit();
    }

    for (int t = 0; t < TS; t++) {
        if (t + 1 < TS) {
            int buf = (t + 1) & 1;
            int k0 = (t + 1) * 32;
            cp16b(&S.Ah[buf][ld_dst], gx0h + k0, ap0);
            cp16b(&S.Al[buf][ld_dst], gx0l + k0, ap0);
            cp16b(&S.Ah[buf][ld_dst + 64 * AS2], gx1h + k0, ap1);
            cp16b(&S.Al[buf][ld_dst + 64 * AS2], gx1l + k0, ap1);
            cp16b(&S.Bgh[buf][ld_dst], gbgh + k0, true);
            cp16b(&S.Bgl[buf][ld_dst], gbgl + k0, true);
            cp16b(&S.Buh[buf][ld_dst], gbuh + k0, true);
            cp16b(&S.Bul[buf][ld_dst], gbul + k0, true);
            cp_commit();
            cp_wait<1>();
        } else {
            cp_wait<0>();
        }
        __syncthreads();

        int buf = t & 1;
        const __nv_bfloat16* ah  = S.Ah[buf];
        const __nv_bfloat16* al  = S.Al[buf];
        const __nv_bfloat16* bgh = S.Bgh[buf];
        const __nv_bfloat16* bgl = S.Bgl[buf];
        const __nv_bfloat16* buh = S.Buh[buf];
        const __nv_bfloat16* bul = S.Bul[buf];

        #pragma unroll
        for (int sub = 0; sub < 2; sub++) {
            int ko = sub * 16;
            uint32_t afh[4][4], afl[4][4];
            #pragma unroll
            for (int mi = 0; mi < 4; mi++) {
                int ro = (wm0 + mi * 16) * AS2 + ko + a_loff;
                ldsm4(afh[mi][0], afh[mi][1], afh[mi][2], afh[mi][3], &ah[ro]);
                ldsm4(afl[mi][0], afl[mi][1], afl[mi][2], afl[mi][3], &al[ro]);
            }
            int bo = wn0 * AS2 + ko + b_loff;
            uint32_t gh[4], gl[4], uh[4], ul[4];
            ldsm4(gh[0], gh[1], gh[2], gh[3], &bgh[bo]);
            ldsm4(gl[0], gl[1], gl[2], gl[3], &bgl[bo]);
            ldsm4(uh[0], uh[1], uh[2], uh[3], &buh[bo]);
            ldsm4(ul[0], ul[1], ul[2], ul[3], &bul[bo]);
            #pragma unroll
            for (int ni = 0; ni < 2; ni++) {
                uint32_t bgh0 = gh[ni * 2], bgh1 = gh[ni * 2 + 1];
                uint32_t bgl0 = gl[ni * 2], bgl1 = gl[ni * 2 + 1];
                uint32_t buh0 = uh[ni * 2], buh1 = uh[ni * 2 + 1];
                uint32_t bul0 = ul[ni * 2], bul1 = ul[ni * 2 + 1];
                #pragma unroll
                for (int mi = 0; mi < 4; mi++) {
                    mma_bf16(accG[mi][ni], afh[mi][0], afh[mi][1], afh[mi][2], afh[mi][3], bgh0, bgh1);
                    mma_bf16(accG[mi][ni], afh[mi][0], afh[mi][1], afh[mi][2], afh[mi][3], bgl0, bgl1);
                    mma_bf16(accG[mi][ni], afl[mi][0], afl[mi][1], afl[mi][2], afl[mi][3], bgh0, bgh1);
                    mma_bf16(accU[mi][ni], afh[mi][0], afh[mi][1], afh[mi][2], afh[mi][3], buh0, buh1);
                    mma_bf16(accU[mi][ni], afh[mi][0], afh[mi][1], afh[mi][2], afh[mi][3], bul0, bul1);
                    mma_bf16(accU[mi][ni], afl[mi][0], afl[mi][1], afl[mi][2], afl[mi][3], buh0, buh1);
                }
            }
        }
        __syncthreads();
    }

    // epilogue: silu(g)*u -> split bf16 planes of H
    #pragma unroll
    for (int mi = 0; mi < 4; mi++) {
        #pragma unroll
        for (int ni = 0; ni < 2; ni++) {
            int col = n0 + wn0 + ni * 8 + tg * 2;
            #pragma unroll
            for (int half = 0; half < 2; half++) {
                int r = m0 + wm0 + mi * 16 + g + half * 8;
                if (r < cnt) {
                    size_t out = (size_t)(base + r) * I_DIM + col;
                    float gv0 = accG[mi][ni][half * 2];
                    float gv1 = accG[mi][ni][half * 2 + 1];
                    float h0 = gv0 / (1.f + expf(-gv0)) * accU[mi][ni][half * 2];
                    float h1 = gv1 / (1.f + expf(-gv1)) * accU[mi][ni][half * 2 + 1];
                    __nv_bfloat16 H0 = __float2bfloat16_rn(h0);
                    __nv_bfloat16 H1 = __float2bfloat16_rn(h1);
                    __nv_bfloat16 L0 = __float2bfloat16_rn(h0 - __bfloat162float(H0));
                    __nv_bfloat16 L1 = __float2bfloat16_rn(h1 - __bfloat162float(H1));
                    *(__nv_bfloat162*)&s_H[0][out] = __halves2bfloat162(H0, H1);
                    *(__nv_bfloat162*)&s_H[1][out] = __halves2bfloat162(L0, L1);
                }
            }
        }
    }
}

// =============================================================================
// gemm2: Ypart = prob * (H @ Wd^T) — split bf16, 3-MMA, ldmatrix, K=32
// Block 128(M) x 128(N) x 32(K), 256 threads, warp tile 64x32.
// =============================================================================
struct Smem2 {
    __nv_bfloat16 Ah[2][128 * AS2], Al[2][128 * AS2];
    __nv_bfloat16 Bh[2][128 * AS2], Bl[2][128 * AS2];
    float rowprob[128];
};

__global__ __launch_bounds__(256) void gemm2_kernel() {
    extern __shared__ char smem_raw[];
    Smem2& S = *reinterpret_cast<Smem2*>(smem_raw);

    int e  = blockIdx.y >> 6;
    int mt = blockIdx.y & (MT_MAX - 1);
    int cnt = d_counts[e];
    int m0  = mt * 128;
    if (m0 >= cnt) return;
    int n0   = blockIdx.x * 128;
    int base = d_offsets[e];

    int tid = threadIdx.x;
    if (tid < 128) {
        int r = m0 + tid;
        S.rowprob[tid] = (r < cnt) ? d_pair_prob[base + r] : 0.f;
    }
    __syncthreads();

    int ld_row = tid >> 2;
    int ld_c   = (tid & 3) * 8;
    bool av0 = (m0 + ld_row) < cnt;
    bool av1 = (m0 + ld_row + 64) < cnt;
    size_t ar0 = (size_t)(base + (av0 ? m0 + ld_row : 0)) * I_DIM + ld_c;
    size_t ar1 = (size_t)(base + (av1 ? m0 + ld_row + 64 : 0)) * I_DIM + ld_c;
    const __nv_bfloat16* ga0h = s_H[0] + ar0;
    const __nv_bfloat16* ga0l = s_H[1] + ar0;
    const __nv_bfloat16* ga1h = s_H[0] + ar1;
    const __nv_bfloat16* ga1l = s_H[1] + ar1;

    size_t wE = (size_t)e * D_DIM * I_DIM;
    size_t br0 = wE + (size_t)(n0 + ld_row) * I_DIM + ld_c;
    size_t br1 = wE + (size_t)(n0 + ld_row + 64) * I_DIM + ld_c;
    const __nv_bfloat16* gb0h = s_wd[0] + br0;
    const __nv_bfloat16* gb0l = s_wd[1] + br0;
    const __nv_bfloat16* gb1h = s_wd[0] + br1;
    const __nv_bfloat16* gb1l = s_wd[1] + br1;

    int wid = tid >> 5, lane = tid & 31;
    int wm0 = (wid >> 2) * 64, wn0 = (wid & 3) * 32;
    int a_loff = ((lane & 7) + ((lane >> 3) & 1) * 8) * AS2 + ((lane >> 4) & 1) * 8;
    int b_loff = ((lane & 7) + ((lane >> 4) & 1) * 8) * AS2 + ((lane >> 3) & 1) * 8;
    int g  = lane >> 2, tg = lane & 3;

    float acc[4][4][4];
    #pragma unroll
    for (int i = 0; i < 4; i++)
        #pragma unroll
        for (int j = 0; j < 4; j++)
            #pragma unroll
            for (int k = 0; k < 4; k++) acc[i][j][k] = 0.f;

    const int TS = I_DIM / 32;   // 44 stages
    int ld_dst = ld_row * AS2 + ld_c;

    {
        cp16b(&S.Ah[0][ld_dst], ga0h, av0);
        cp16b(&S.Al[0][ld_dst], ga0l, av0);
        cp16b(&S.Ah[0][ld_dst + 64 * AS2], ga1h, av1);
        cp16b(&S.Al[0][ld_dst + 64 * AS2], ga1l, av1);
        cp16b(&S.Bh[0][ld_dst], gb0h, true);
        cp16b(&S.Bl[0][ld_dst], gb0l, true);
        cp16b(&S.Bh[0][ld_dst + 64 * AS2], gb1h, true);
        cp16b(&S.Bl[0][ld_dst + 64 * AS2], gb1l, true);
        cp_commit();
    }

    for (int t = 0; t < TS; t++) {
        if (t + 1 < TS) {
            int buf = (t + 1) & 1;
            int k0 = (t + 1) * 32;
            cp16b(&S.Ah[buf][ld_dst], ga0h + k0, av0);
            cp16b(&S.Al[buf][ld_dst], ga0l + k0, av0);
            cp16b(&S.Ah[buf][ld_dst + 64 * AS2], ga1h + k0, av1);
            cp16b(&S.Al[buf][ld_dst + 64 * AS2], ga1l + k0, av1);
            cp16b(&S.Bh[buf][ld_dst], gb0h + k0, true);
            cp16b(&S.Bl[buf][ld_dst], gb0l + k0, true);
            cp16b(&S.Bh[buf][ld_dst + 64 * AS2], gb1h + k0, true);
            cp16b(&S.Bl[buf][ld_dst + 64 * AS2], gb1l + k0, true);
            cp_commit();
            cp_wait<1>();
        } else {
            cp_wait<0>();
        }
        __syncthreads();

        int buf = t & 1;
        const __nv_bfloat16* ah = S.Ah[buf];
        const __nv_bfloat16* al = S.Al[buf];
        const __nv_bfloat16* bh = S.Bh[buf];
        const __nv_bfloat16* bl = S.Bl[buf];

        #pragma unroll
        for (int sub = 0; sub < 2; sub++) {
            int ko = sub * 16;
            uint32_t afh[4][4], afl[4][4];
            #pragma unroll
            for (int mi = 0; mi < 4; mi++) {
                int ro = (wm0 + mi * 16) * AS2 + ko + a_loff;
                ldsm4(afh[mi][0], afh[mi][1], afh[mi][2], afh[mi][3], &ah[ro]);
                ldsm4(afl[mi][0], afl[mi][1], afl[mi][2], afl[mi][3], &al[ro]);
            }
            uint32_t bhr[2][4], blr[2][4];
            #pragma unroll
            for (int half = 0; half < 2; half++) {
                int bo = (wn0 + half * 16) * AS2 + ko + b_loff;
                ldsm4(bhr[half][0], bhr[half][1], bhr[half][2], bhr[half][3], &bh[bo]);
                ldsm4(blr[half][0], blr[half][1], blr[half][2], blr[half][3], &bl[bo]);
            }
            #pragma unroll
            for (int ni = 0; ni < 4; ni++) {
                uint32_t b0h = bhr[ni >> 1][(ni & 1) * 2], b1h = bhr[ni >> 1][(ni & 1) * 2 + 1];
                uint32_t b0l = blr[ni >> 1][(ni & 1) * 2], b1l = blr[ni >> 1][(ni & 1) * 2 + 1];
                #pragma unroll
                for (int mi = 0; mi < 4; mi++) {
                    mma_bf16(acc[mi][ni], afh[mi][0], afh[mi][1], afh[mi][2], afh[mi][3], b0h, b1h);
                    mma_bf16(acc[mi][ni], afh[mi][0], afh[mi][1], afh[mi][2], afh[mi][3], b0l, b1l);
                    mma_bf16(acc[mi][ni], afl[mi][0], afl[mi][1], afl[mi][2], afl[mi][3], b0h, b1h);
                }
            }
        }
        __syncthreads();
    }

    // epilogue: scale by prob -> d_Ypart (fp32)
    #pragma unroll
    for (int mi = 0; mi < 4; mi++) {
        #pragma unroll
        for (int half = 0; half < 2; half++) {
            int rb = wm0 + mi * 16 + g + half * 8;
            int r  = m0 + rb;
            if (r >= cnt) continue;
            float p = S.rowprob[rb];
            size_t out = (size_t)(base + r) * D_DIM + n0 + wn0;
            #pragma unroll
            for (int ni = 0; ni < 4; ni++) {
                int col = ni * 8 + tg * 2;
                d_Ypart[out + col]     = p * acc[mi][ni][half * 2];
                d_Ypart[out + col + 1] = p * acc[mi][ni][half * 2 + 1];
            }
        }
    }
}

// ---------------- combine ----------------------------------------------------
__global__ void combine_kernel(float* __restrict__ y) {
    int i = blockIdx.x * blockDim.x + threadIdx.x;
    int t = i / (D_DIM / 4);
    int c = (i % (D_DIM / 4)) * 4;
    int p0 = d_pair_pos[t * 2];
    int p1 = d_pair_pos[t * 2 + 1];
    float4 a = *(const float4*)&d_Ypart[(size_t)p0 * D_DIM + c];
    float4 b = *(const float4*)&d_Ypart[(size_t)p1 * D_DIM + c];
    float4 o = make_float4(a.x + b.x, a.y + b.y, a.z + b.z, a.w + b.w);
    *(float4*)&y[(size_t)t * D_DIM + c] = o;
}

// ---------------- launch -----------------------------------------------------
extern "C" void kernel_launch(void* const* d_in, const int* in_sizes, int n_in,
                              void* d_out, int out_size) {
    const float* x  = (const float*)d_in[0];
    const float* gw = (const float*)d_in[1];
    const float* wg = (const float*)d_in[2];
    const float* wu = (const float*)d_in[3];
    const float* wd = (const float*)d_in[4];
    float* y = (float*)d_out;

    cudaFuncSetAttribute(gemm1_kernel, cudaFuncAttributeMaxDynamicSharedMemorySize, sizeof(Smem1));
    cudaFuncSetAttribute(gemm2_kernel, cudaFuncAttributeMaxDynamicSharedMemorySize, sizeof(Smem2));

    __nv_bfloat16 *p_x, *p_wg, *p_wu, *p_wd;
    cudaGetSymbolAddress((void**)&p_x,  s_x);
    cudaGetSymbolAddress((void**)&p_wg, s_wg);
    cudaGetSymbolAddress((void**)&p_wu, s_wu);
    cudaGetSymbolAddress((void**)&p_wd, s_wd);
    size_t xN = (size_t)N_TOK * D_DIM;

    init_kernel<<<1, 32>>>();
    router_kernel<<<N_TOK, 256>>>(x, gw);

    {   // splits
        int n4 = (int)(xN / 4);
        split_kernel<<<(n4 + 255) / 256, 256>>>((const float4*)x, (uint2*)p_x, (uint2*)(p_x + xN), n4);
        int w4 = (int)(W_ELEMS / 4);
        const float* wsrc[3] = {wg, wu, wd};
        __nv_bfloat16* wdst[3] = {p_wg, p_wu, p_wd};
        for (int m = 0; m < 3; m++)
            split_kernel<<<(w4 + 255) / 256, 256>>>((const float4*)wsrc[m],
                                                    (uint2*)wdst[m],
                                                    (uint2*)(wdst[m] + W_ELEMS), w4);
    }

    scan_kernel<<<1, 1>>>();
    scatter_kernel<<<(N_TOK + 255) / 256, 256>>>();
    gemm1_kernel<<<dim3(I_DIM / 64, E_NUM * MT_MAX), 256, sizeof(Smem1)>>>();
    gemm2_kernel<<<dim3(D_DIM / 128, E_NUM * MT_MAX), 256, sizeof(Smem2)>>>();
    combine_kernel<<<(N_TOK * D_DIM / 4 + 255) / 256, 256>>>(y);
}